// round 6
// baseline (speedup 1.0000x reference)
#include <cuda_runtime.h>
#include <math.h>

// Problem constants: B=4, N=16, K=16, H=64, O=1
#define ZB 4
#define NN 16
#define NK 16
#define NH 64

// h accumulator: [z*16+a][h] = 4096 floats (16 KB). Statically zero at load;
// every launch re-zeroes it in the finisher block -> replay-invariant.
__device__ float    g_h[ZB * NN * NH];
__device__ unsigned g_count;               // completion counter, reset by finisher

// ---------------------------------------------------------------------------
// Inline basis eval: P[z,i,j,k,:] = cutoff*exp(-beta*(exp(-norm)-mean_k)^2)
//                                   * diff / norm_sq
// ---------------------------------------------------------------------------
__device__ __forceinline__ float3 smear_vec(const float* __restrict__ xi,
                                            const float* __restrict__ xj,
                                            int k) {
    float d0 = xi[0] - xj[0];
    float d1 = xi[1] - xj[1];
    float d2 = xi[2] - xj[2];

    float ns = d0 * d0 + d1 * d1 + d2 * d2 + 1e-5f;
    float norm = sqrtf(ns);

    const float start = expf(-5.0f);                 // literal, const-folded
    float mean = start + (float)k * (1.0f - start) * (1.0f / 15.0f);
    float bden = 0.125f * (1.0f - start);
    float beta = 1.0f / (bden * bden);

    float cutoff = (norm < 5.0f)
                 ? 0.5f * (cospif(norm * 0.2f) + 1.0f)
                 : 0.0f;
    float e = expf(-norm);
    float dd = e - mean;
    float smear = cutoff * expf(-beta * dd * dd);
    float so = smear / ns;
    return make_float3(so * d0, so * d1, so * d2);
}

// ---------------------------------------------------------------------------
// Single fused kernel. 512 blocks = 16 a-groups x 32 sub-blocks, one wave.
// Block (a,sub) streams 8 slices (b,d) of W (512 KB) barrier-free with all
// coef tables precomputed, atomically accumulates into g_h, and the LAST
// block to finish computes the 64 silu+fc outputs and re-zeroes g_h.
// ---------------------------------------------------------------------------
__global__ void __launch_bounds__(256, 4) k_fused(const float* __restrict__ W,
                                                  const float* __restrict__ x,
                                                  const float* __restrict__ w_fc,
                                                  const float* __restrict__ b_fc,
                                                  float* __restrict__ out) {
    __shared__ float  sx[ZB * NN * 3];         // coords, 768 B
    __shared__ float  sAux[8 * 256];           // 8 KB: P1 table first, sred later
    __shared__ float4 scoef[8 * 256];          // 32 KB: [s][j=e*16+k] -> (z0..z3)
    __shared__ unsigned s_old;

    int a   = blockIdx.x >> 5;                 // 0..15
    int sub = blockIdx.x & 31;                 // 0..31
    int d   = sub & 15;                        // fixed across slices

    int t  = threadIdx.x;
    int h4 = t & 15;                           // float4 index within 64 h
    int g  = t >> 4;                           // j-row group 0..15

    // --- load coords ---
    if (t < ZB * NN * 3) sx[t] = x[t];
    __syncthreads();

    // --- cooperative P1[s][k][z] = P[z,a,b_s,k,:], 512 evals, 2 per thread ---
    for (int i = t; i < 512; i += 256) {
        int s = i >> 6;                        // 0..7
        int k = (i >> 2) & 15;
        int z = i & 3;
        int b = (sub >> 4) + (s << 1);         // b of slice s
        float3 v = smear_vec(&sx[(z * NN + a) * 3], &sx[(z * NN + b) * 3], k);
        float* p = &sAux[i * 3];
        p[0] = v.x; p[1] = v.y; p[2] = v.z;
    }
    __syncthreads();

    // --- per-thread P2[z] = P[z,d,e,k,:] and all 8 coef tables ---
    {
        int e = t >> 4;
        int k = t & 15;
        float3 p2[4];
#pragma unroll
        for (int z = 0; z < 4; z++)
            p2[z] = smear_vec(&sx[(z * NN + d) * 3], &sx[(z * NN + e) * 3], k);

#pragma unroll
        for (int s = 0; s < 8; s++) {
            float cf[4];
#pragma unroll
            for (int z = 0; z < 4; z++) {
                const float* p1 = &sAux[((s * 16 + k) * 4 + z) * 3];
                cf[z] = p1[0] * p2[z].x + p1[1] * p2[z].y + p1[2] * p2[z].z;
            }
            scoef[s * 256 + t] = make_float4(cf[0], cf[1], cf[2], cf[3]);
        }
    }
    __syncthreads();                           // coef tables ready; last block sync

    // --- barrier-free stream: 8 slices x 64 KB ---
    const float4* Wbase = (const float4*)W
                        + (((size_t)a * 256 + sub) << 12) + (g * 16 + h4);

    float acc0x = 0.f, acc0y = 0.f, acc0z = 0.f, acc0w = 0.f;
    float acc1x = 0.f, acc1y = 0.f, acc1z = 0.f, acc1w = 0.f;
    float acc2x = 0.f, acc2y = 0.f, acc2z = 0.f, acc2w = 0.f;
    float acc3x = 0.f, acc3y = 0.f, acc3z = 0.f, acc3w = 0.f;

#pragma unroll 1
    for (int s = 0; s < 8; s++) {
        const float4* Wp = Wbase + ((size_t)s << 17);   // +32 slices * 4096 float4
        const float4* cp = scoef + s * 256;

#pragma unroll
        for (int it = 0; it < 16; it += 4) {
            float4 w0 = __ldcs(Wp + (size_t)(it + 0) * 256);
            float4 w1 = __ldcs(Wp + (size_t)(it + 1) * 256);
            float4 w2 = __ldcs(Wp + (size_t)(it + 2) * 256);
            float4 w3 = __ldcs(Wp + (size_t)(it + 3) * 256);

            float4 c;
            c = cp[g + (it + 0) * 16];
            acc0x += c.x * w0.x; acc0y += c.x * w0.y; acc0z += c.x * w0.z; acc0w += c.x * w0.w;
            acc1x += c.y * w0.x; acc1y += c.y * w0.y; acc1z += c.y * w0.z; acc1w += c.y * w0.w;
            acc2x += c.z * w0.x; acc2y += c.z * w0.y; acc2z += c.z * w0.z; acc2w += c.z * w0.w;
            acc3x += c.w * w0.x; acc3y += c.w * w0.y; acc3z += c.w * w0.z; acc3w += c.w * w0.w;

            c = cp[g + (it + 1) * 16];
            acc0x += c.x * w1.x; acc0y += c.x * w1.y; acc0z += c.x * w1.z; acc0w += c.x * w1.w;
            acc1x += c.y * w1.x; acc1y += c.y * w1.y; acc1z += c.y * w1.z; acc1w += c.y * w1.w;
            acc2x += c.z * w1.x; acc2y += c.z * w1.y; acc2z += c.z * w1.z; acc2w += c.z * w1.w;
            acc3x += c.w * w1.x; acc3y += c.w * w1.y; acc3z += c.w * w1.z; acc3w += c.w * w1.w;

            c = cp[g + (it + 2) * 16];
            acc0x += c.x * w2.x; acc0y += c.x * w2.y; acc0z += c.x * w2.z; acc0w += c.x * w2.w;
            acc1x += c.y * w2.x; acc1y += c.y * w2.y; acc1z += c.y * w2.z; acc1w += c.y * w2.w;
            acc2x += c.z * w2.x; acc2y += c.z * w2.y; acc2z += c.z * w2.z; acc2w += c.z * w2.w;
            acc3x += c.w * w2.x; acc3y += c.w * w2.y; acc3z += c.w * w2.z; acc3w += c.w * w2.w;

            c = cp[g + (it + 3) * 16];
            acc0x += c.x * w3.x; acc0y += c.x * w3.y; acc0z += c.x * w3.z; acc0w += c.x * w3.w;
            acc1x += c.y * w3.x; acc1y += c.y * w3.y; acc1z += c.y * w3.z; acc1w += c.y * w3.w;
            acc2x += c.z * w3.x; acc2y += c.z * w3.y; acc2z += c.z * w3.z; acc2w += c.z * w3.w;
            acc3x += c.w * w3.x; acc3y += c.w * w3.y; acc3z += c.w * w3.z; acc3w += c.w * w3.w;
        }
    }

    // --- epilogue: shfl-combine g pairs, 8-warp smem reduce, atomic to g_h ---
#define SHFL_ADD(v) v += __shfl_xor_sync(0xFFFFFFFFu, v, 16)
    SHFL_ADD(acc0x); SHFL_ADD(acc0y); SHFL_ADD(acc0z); SHFL_ADD(acc0w);
    SHFL_ADD(acc1x); SHFL_ADD(acc1y); SHFL_ADD(acc1z); SHFL_ADD(acc1w);
    SHFL_ADD(acc2x); SHFL_ADD(acc2y); SHFL_ADD(acc2z); SHFL_ADD(acc2w);
    SHFL_ADD(acc3x); SHFL_ADD(acc3y); SHFL_ADD(acc3z); SHFL_ADD(acc3w);
#undef SHFL_ADD

    // sAux reuse as sred is safe: its last reads were before the coef sync.
    int lane = t & 31;
    int wrp  = t >> 5;                         // 0..7
    if (lane < 16) {
        float4* r4 = (float4*)sAux;            // [8 warps][4 z][16 h4] of float4
        int base = (wrp * 4) * 16 + h4;
        r4[base + 0 * 16] = make_float4(acc0x, acc0y, acc0z, acc0w);
        r4[base + 1 * 16] = make_float4(acc1x, acc1y, acc1z, acc1w);
        r4[base + 2 * 16] = make_float4(acc2x, acc2y, acc2z, acc2w);
        r4[base + 3 * 16] = make_float4(acc3x, acc3y, acc3z, acc3w);
    }
    __syncthreads();

    float sum = 0.0f;
#pragma unroll
    for (int w2 = 0; w2 < 8; w2++) sum += sAux[w2 * 256 + t];

    {
        int z = t >> 6;
        int h = t & 63;
        atomicAdd(&g_h[(z * NN + a) * NH + h], sum);
    }

    // --- last-block-done: finisher computes outputs and re-zeroes g_h ---
    __threadfence();
    if (t == 0) s_old = atomicAdd(&g_count, 1);
    __syncthreads();

    if (s_old == 511u) {
        if (t == 0) g_count = 0u;              // reset for next launch/replay

        if (t < ZB * NN) {                     // t = z*16+a
            const float* hp = &g_h[t * NH];
            float acc = 0.0f;
#pragma unroll
            for (int h = 0; h < NH; h++) {
                float v = __ldcg(&hp[h]);      // L2-fresh (bypass L1)
                float sg = v / (1.0f + expf(-v));
                acc += sg * w_fc[h];
            }
            out[t] = acc + b_fc[0];
        }
        __syncthreads();                       // reads done before re-zero

        for (int i = t; i < ZB * NN * NH; i += 256) g_h[i] = 0.0f;
    }
}

// ---------------------------------------------------------------------------
extern "C" void kernel_launch(void* const* d_in, const int* in_sizes, int n_in,
                              void* d_out, int out_size) {
    const float* x   = nullptr;
    const float* W   = nullptr;
    const float* wfc = nullptr;
    const float* bfc = nullptr;
    for (int i = 0; i < n_in; i++) {
        long long s = in_sizes[i];
        if      (s == (long long)ZB * NN * 3)                 x   = (const float*)d_in[i];
        else if (s == (long long)NN * NN * NN * NN * NK * NH) W   = (const float*)d_in[i];
        else if (s == NH)                                     wfc = (const float*)d_in[i];
        else if (s == 1)                                      bfc = (const float*)d_in[i];
    }

    k_fused<<<512, 256>>>(W, x, wfc, bfc, (float*)d_out);
}

// round 8
// speedup vs baseline: 1.3894x; 1.3894x over previous
#include <cuda_runtime.h>
#include <math.h>

// Problem constants: B=4, N=16, K=16, H=64, O=1
#define ZB 4
#define NN 16
#define NK 16
#define NH 64

// Per-block partials: [a(16)][sub(32)][z*64+h(256)] = 512 KB.
// Fully overwritten every launch by plain STG -> no init, no atomics.
__device__ float    g_part[16 * 32 * 256];
// Per-a-group completion counters; statically 0, reset by each finisher.
__device__ unsigned g_count[16];

// ---------------------------------------------------------------------------
// Inline basis eval: P[z,i,j,k,:] = cutoff*exp(-beta*(exp(-norm)-mean_k)^2)
//                                   * diff / norm_sq
// ---------------------------------------------------------------------------
__device__ __forceinline__ float3 smear_vec(const float* __restrict__ xi,
                                            const float* __restrict__ xj,
                                            int k) {
    float d0 = xi[0] - xj[0];
    float d1 = xi[1] - xj[1];
    float d2 = xi[2] - xj[2];

    float ns = d0 * d0 + d1 * d1 + d2 * d2 + 1e-5f;
    float norm = sqrtf(ns);

    const float start = expf(-5.0f);                 // literal, const-folded
    float mean = start + (float)k * (1.0f - start) * (1.0f / 15.0f);
    float bden = 0.125f * (1.0f - start);
    float beta = 1.0f / (bden * bden);

    float cutoff = (norm < 5.0f)
                 ? 0.5f * (cospif(norm * 0.2f) + 1.0f)
                 : 0.0f;
    float e = expf(-norm);
    float dd = e - mean;
    float smear = cutoff * expf(-beta * dd * dd);
    float so = smear / ns;
    return make_float3(so * d0, so * d1, so * d2);
}

// ---------------------------------------------------------------------------
// Per-a-group finisher: reduce 32 partials (32 KB, L2), silu, dot with w_fc,
// write out[z*16+a] for z=0..3, reset this group's counter.
// __noinline__ so its register demand cannot inflate the hot loop.
// ---------------------------------------------------------------------------
__device__ __noinline__ void finish_group(int a,
                                          const float* __restrict__ w_fc,
                                          const float* __restrict__ b_fc,
                                          float* __restrict__ out,
                                          float* sred) {
    int t = threadIdx.x;                       // t = z*64 + h

    __threadfence();                           // acquire side vs other blocks' STGs

    const float* p = &g_part[(a * 32) * 256 + t];
    float v = 0.0f;
#pragma unroll
    for (int sub = 0; sub < 32; sub++) v += __ldcg(p + sub * 256);

    float sg = (v / (1.0f + expf(-v))) * w_fc[t & 63];

    // warp-reduce 32 lanes; warp w covers z = w>>1 (two warps per z)
#pragma unroll
    for (int o = 16; o > 0; o >>= 1) sg += __shfl_xor_sync(0xFFFFFFFFu, sg, o);
    if ((t & 31) == 0) sred[t >> 5] = sg;      // 8 partials
    __syncthreads();

    if (t < ZB) out[t * NN + a] = sred[2 * t] + sred[2 * t + 1] + b_fc[0];
    if (t == 0) g_count[a] = 0u;               // reset for next launch/replay
}

// ---------------------------------------------------------------------------
// Single fused kernel. 512 blocks = 16 a-groups x 32 sub-blocks, one wave.
// Block (a,sub) streams 8 slices (b,d) of W (512 KB) barrier-free with all
// coef tables precomputed; plain STG of a 1 KB partial; the 32nd block of
// each a-group finishes that group's outputs.
// ---------------------------------------------------------------------------
__global__ void __launch_bounds__(256, 4) k_fused(const float* __restrict__ W,
                                                  const float* __restrict__ x,
                                                  const float* __restrict__ w_fc,
                                                  const float* __restrict__ b_fc,
                                                  float* __restrict__ out) {
    __shared__ __align__(16) float  sx[ZB * NN * 3];   // coords, 768 B
    __shared__ __align__(16) float  sAux[8 * 256];     // 8 KB: P1 table, then sred
    __shared__ float4 scoef[8 * 256];                  // 32 KB: [s][j] -> (z0..z3)
    __shared__ unsigned s_old;

    int a   = blockIdx.x >> 5;                 // 0..15
    int sub = blockIdx.x & 31;                 // 0..31
    int d   = sub & 15;                        // fixed across slices

    int t  = threadIdx.x;
    int h4 = t & 15;                           // float4 index within 64 h
    int g  = t >> 4;                           // j-row group 0..15

    // --- load coords ---
    if (t < ZB * NN * 3) sx[t] = x[t];
    __syncthreads();

    // --- cooperative P1[s][k][z] = P[z,a,b_s,k,:], 512 evals, 2 per thread ---
    for (int i = t; i < 512; i += 256) {
        int s = i >> 6;                        // 0..7
        int k = (i >> 2) & 15;
        int z = i & 3;
        int b = (sub >> 4) + (s << 1);         // b of slice s
        float3 v = smear_vec(&sx[(z * NN + a) * 3], &sx[(z * NN + b) * 3], k);
        float* p = &sAux[i * 3];
        p[0] = v.x; p[1] = v.y; p[2] = v.z;
    }
    __syncthreads();

    // --- per-thread P2[z] = P[z,d,e,k,:] and all 8 coef tables ---
    {
        int e = t >> 4;
        int k = t & 15;
        float3 p2[4];
#pragma unroll
        for (int z = 0; z < 4; z++)
            p2[z] = smear_vec(&sx[(z * NN + d) * 3], &sx[(z * NN + e) * 3], k);

#pragma unroll
        for (int s = 0; s < 8; s++) {
            float cf[4];
#pragma unroll
            for (int z = 0; z < 4; z++) {
                const float* p1 = &sAux[((s * 16 + k) * 4 + z) * 3];
                cf[z] = p1[0] * p2[z].x + p1[1] * p2[z].y + p1[2] * p2[z].z;
            }
            scoef[s * 256 + t] = make_float4(cf[0], cf[1], cf[2], cf[3]);
        }
    }
    __syncthreads();                           // coef tables ready; mainloop sync-free

    // --- barrier-free stream: 8 slices x 64 KB ---
    const float4* Wbase = (const float4*)W
                        + (((size_t)a * 256 + sub) << 12) + (g * 16 + h4);

    float acc0x = 0.f, acc0y = 0.f, acc0z = 0.f, acc0w = 0.f;
    float acc1x = 0.f, acc1y = 0.f, acc1z = 0.f, acc1w = 0.f;
    float acc2x = 0.f, acc2y = 0.f, acc2z = 0.f, acc2w = 0.f;
    float acc3x = 0.f, acc3y = 0.f, acc3z = 0.f, acc3w = 0.f;

#pragma unroll 1
    for (int s = 0; s < 8; s++) {
        const float4* Wp = Wbase + ((size_t)s << 17);   // +32 slices * 4096 float4
        const float4* cp = scoef + s * 256;

#pragma unroll
        for (int it = 0; it < 16; it += 4) {
            float4 w0 = __ldcs(Wp + (size_t)(it + 0) * 256);
            float4 w1 = __ldcs(Wp + (size_t)(it + 1) * 256);
            float4 w2 = __ldcs(Wp + (size_t)(it + 2) * 256);
            float4 w3 = __ldcs(Wp + (size_t)(it + 3) * 256);

            float4 c;
            c = cp[g + (it + 0) * 16];
            acc0x += c.x * w0.x; acc0y += c.x * w0.y; acc0z += c.x * w0.z; acc0w += c.x * w0.w;
            acc1x += c.y * w0.x; acc1y += c.y * w0.y; acc1z += c.y * w0.z; acc1w += c.y * w0.w;
            acc2x += c.z * w0.x; acc2y += c.z * w0.y; acc2z += c.z * w0.z; acc2w += c.z * w0.w;
            acc3x += c.w * w0.x; acc3y += c.w * w0.y; acc3z += c.w * w0.z; acc3w += c.w * w0.w;

            c = cp[g + (it + 1) * 16];
            acc0x += c.x * w1.x; acc0y += c.x * w1.y; acc0z += c.x * w1.z; acc0w += c.x * w1.w;
            acc1x += c.y * w1.x; acc1y += c.y * w1.y; acc1z += c.y * w1.z; acc1w += c.y * w1.w;
            acc2x += c.z * w1.x; acc2y += c.z * w1.y; acc2z += c.z * w1.z; acc2w += c.z * w1.w;
            acc3x += c.w * w1.x; acc3y += c.w * w1.y; acc3z += c.w * w1.z; acc3w += c.w * w1.w;

            c = cp[g + (it + 2) * 16];
            acc0x += c.x * w2.x; acc0y += c.x * w2.y; acc0z += c.x * w2.z; acc0w += c.x * w2.w;
            acc1x += c.y * w2.x; acc1y += c.y * w2.y; acc1z += c.y * w2.z; acc1w += c.y * w2.w;
            acc2x += c.z * w2.x; acc2y += c.z * w2.y; acc2z += c.z * w2.z; acc2w += c.z * w2.w;
            acc3x += c.w * w2.x; acc3y += c.w * w2.y; acc3z += c.w * w2.z; acc3w += c.w * w2.w;

            c = cp[g + (it + 3) * 16];
            acc0x += c.x * w3.x; acc0y += c.x * w3.y; acc0z += c.x * w3.z; acc0w += c.x * w3.w;
            acc1x += c.y * w3.x; acc1y += c.y * w3.y; acc1z += c.y * w3.z; acc1w += c.y * w3.w;
            acc2x += c.z * w3.x; acc2y += c.z * w3.y; acc2z += c.z * w3.z; acc2w += c.z * w3.w;
            acc3x += c.w * w3.x; acc3y += c.w * w3.y; acc3z += c.w * w3.z; acc3w += c.w * w3.w;
        }
    }

    // --- epilogue: shfl-combine g pairs, 8-warp smem reduce, plain STG ---
#define SHFL_ADD(v) v += __shfl_xor_sync(0xFFFFFFFFu, v, 16)
    SHFL_ADD(acc0x); SHFL_ADD(acc0y); SHFL_ADD(acc0z); SHFL_ADD(acc0w);
    SHFL_ADD(acc1x); SHFL_ADD(acc1y); SHFL_ADD(acc1z); SHFL_ADD(acc1w);
    SHFL_ADD(acc2x); SHFL_ADD(acc2y); SHFL_ADD(acc2z); SHFL_ADD(acc2w);
    SHFL_ADD(acc3x); SHFL_ADD(acc3y); SHFL_ADD(acc3z); SHFL_ADD(acc3w);
#undef SHFL_ADD

    // sAux reuse as sred is safe: its last reads were before the coef sync.
    int lane = t & 31;
    int wrp  = t >> 5;                         // 0..7
    if (lane < 16) {
        float4* r4 = (float4*)sAux;            // [8 warps][4 z][16 h4] of float4
        int base = (wrp * 4) * 16 + h4;
        r4[base + 0 * 16] = make_float4(acc0x, acc0y, acc0z, acc0w);
        r4[base + 1 * 16] = make_float4(acc1x, acc1y, acc1z, acc1w);
        r4[base + 2 * 16] = make_float4(acc2x, acc2y, acc2z, acc2w);
        r4[base + 3 * 16] = make_float4(acc3x, acc3y, acc3z, acc3w);
    }
    __syncthreads();

    float sum = 0.0f;
#pragma unroll
    for (int w2 = 0; w2 < 8; w2++) sum += sAux[w2 * 256 + t];

    g_part[blockIdx.x * 256 + t] = sum;        // coalesced STG, no atomic

    // --- per-a-group last-block-done ---
    __threadfence();                           // my STG visible device-wide
    __syncthreads();                           // all threads' fences done
    if (t == 0) s_old = atomicAdd(&g_count[a], 1);
    __syncthreads();

    if (s_old == 31u)
        finish_group(a, w_fc, b_fc, out, sAux);
}

// ---------------------------------------------------------------------------
extern "C" void kernel_launch(void* const* d_in, const int* in_sizes, int n_in,
                              void* d_out, int out_size) {
    const float* x   = nullptr;
    const float* W   = nullptr;
    const float* wfc = nullptr;
    const float* bfc = nullptr;
    for (int i = 0; i < n_in; i++) {
        long long s = in_sizes[i];
        if      (s == (long long)ZB * NN * 3)                 x   = (const float*)d_in[i];
        else if (s == (long long)NN * NN * NN * NN * NK * NH) W   = (const float*)d_in[i];
        else if (s == NH)                                     wfc = (const float*)d_in[i];
        else if (s == 1)                                      bfc = (const float*)d_in[i];
    }

    k_fused<<<512, 256>>>(W, x, wfc, bfc, (float*)d_out);
}

// round 9
// speedup vs baseline: 1.5033x; 1.0819x over previous
#include <cuda_runtime.h>
#include <math.h>

// Problem constants: B=4, N=16, K=16, H=64, O=1
#define ZB 4
#define NN 16
#define NK 16
#define NH 64

// Per-block partials: [a(16)][sub(32)][z*64+h(256)] = 512 KB.
// Fully overwritten every launch by plain STG -> no init, no atomics.
__device__ float    g_part[16 * 32 * 256];
// Per-a-group completion counters; statically 0, reset by each finisher.
__device__ unsigned g_count[16];

// ---------------------------------------------------------------------------
// Inline basis eval (fast intrinsics; tolerance is 1e-3, this is ~1e-6):
// P[z,i,j,k,:] = cutoff*exp(-beta*(exp(-norm)-mean_k)^2) * diff / norm_sq
// ---------------------------------------------------------------------------
__device__ __forceinline__ float3 smear_vec(const float* __restrict__ xi,
                                            const float* __restrict__ xj,
                                            int k) {
    float d0 = xi[0] - xj[0];
    float d1 = xi[1] - xj[1];
    float d2 = xi[2] - xj[2];

    float ns = fmaf(d0, d0, fmaf(d1, d1, fmaf(d2, d2, 1e-5f)));
    float rs = __frsqrt_rn(ns);
    float norm = ns * rs;                            // sqrt(ns)

    const float start = 0.006737946999085467f;       // exp(-5)
    float mean = start + (float)k * (1.0f - start) * (1.0f / 15.0f);
    const float bden = 0.125f * (1.0f - start);
    const float beta = 1.0f / (bden * bden);

    float cutoff = (norm < 5.0f)
                 ? 0.5f * (cospif(norm * 0.2f) + 1.0f)
                 : 0.0f;
    float e = __expf(-norm);
    float dd = e - mean;
    float smear = cutoff * __expf(-beta * dd * dd);
    float so = __fdividef(smear, ns);
    return make_float3(so * d0, so * d1, so * d2);
}

// ---------------------------------------------------------------------------
// Per-a-group finisher: reduce 32 partials (32 KB, L2), silu, dot with w_fc,
// write out[z*16+a] for z=0..3, reset this group's counter.
// __noinline__ so its register demand cannot inflate the hot loop.
// ---------------------------------------------------------------------------
__device__ __noinline__ void finish_group(int a,
                                          const float* __restrict__ w_fc,
                                          const float* __restrict__ b_fc,
                                          float* __restrict__ out,
                                          float* sred) {
    int t = threadIdx.x;                       // t = z*64 + h

    __threadfence();                           // acquire side vs other blocks' STGs

    const float* p = &g_part[(a * 32) * 256 + t];
    float v = 0.0f;
#pragma unroll
    for (int sub = 0; sub < 32; sub++) v += __ldcg(p + sub * 256);

    float sg = (v / (1.0f + __expf(-v))) * w_fc[t & 63];

    // warp-reduce 32 lanes; two warps per z
#pragma unroll
    for (int o = 16; o > 0; o >>= 1) sg += __shfl_xor_sync(0xFFFFFFFFu, sg, o);
    if ((t & 31) == 0) sred[t >> 5] = sg;      // 8 partials
    __syncthreads();

    if (t < ZB) out[t * NN + a] = sred[2 * t] + sred[2 * t + 1] + b_fc[0];
    if (t == 0) g_count[a] = 0u;               // reset for next launch/replay
}

// ---------------------------------------------------------------------------
// Single fused kernel. 512 blocks = 16 a-groups x 32 sub-blocks, one wave.
// Block (a,sub) prefetches its first slice to L2, builds all coef tables,
// streams 8 slices (b,d) of W (512 KB) barrier-free, STGs a 1 KB partial;
// the 32nd block of each a-group finishes that group's outputs.
// ---------------------------------------------------------------------------
__global__ void __launch_bounds__(256, 4) k_fused(const float* __restrict__ W,
                                                  const float* __restrict__ x,
                                                  const float* __restrict__ w_fc,
                                                  const float* __restrict__ b_fc,
                                                  float* __restrict__ out) {
    __shared__ __align__(16) float  sx[ZB * NN * 3];   // coords, 768 B
    __shared__ __align__(16) float  sAux[8 * 256];     // 8 KB: P1 table, then sred
    __shared__ float4 scoef[8 * 256];                  // 32 KB: [s][j] -> (z0..z3)
    __shared__ unsigned s_old;

    int a   = blockIdx.x >> 5;                 // 0..15
    int sub = blockIdx.x & 31;                 // 0..31
    int d   = sub & 15;                        // fixed across slices

    int t  = threadIdx.x;
    int h4 = t & 15;                           // float4 index within 64 h
    int g  = t >> 4;                           // j-row group 0..15

    // --- FIRST: prefetch this block's slice 0 (64 KB = 512 x 128B) to L2,
    //     so DRAM streams while we compute the prologue. ---
    {
        const char* pf = (const char*)((const float4*)W
                       + (((size_t)a * 256 + sub) << 12));
        asm volatile("prefetch.global.L2 [%0];" :: "l"(pf + (size_t)t * 128));
        asm volatile("prefetch.global.L2 [%0];" :: "l"(pf + (size_t)(t + 256) * 128));
    }

    // --- load coords ---
    if (t < ZB * NN * 3) sx[t] = x[t];
    __syncthreads();

    // --- cooperative P1[s][k][z] = P[z,a,b_s,k,:], 512 evals, 2 per thread ---
    for (int i = t; i < 512; i += 256) {
        int s = i >> 6;                        // 0..7
        int k = (i >> 2) & 15;
        int z = i & 3;
        int b = (sub >> 4) + (s << 1);         // b of slice s
        float3 v = smear_vec(&sx[(z * NN + a) * 3], &sx[(z * NN + b) * 3], k);
        float* p = &sAux[i * 3];
        p[0] = v.x; p[1] = v.y; p[2] = v.z;
    }
    __syncthreads();

    // --- per-thread P2[z] = P[z,d,e,k,:] and all 8 coef tables ---
    {
        int e = t >> 4;
        int k = t & 15;
        float3 p2[4];
#pragma unroll
        for (int z = 0; z < 4; z++)
            p2[z] = smear_vec(&sx[(z * NN + d) * 3], &sx[(z * NN + e) * 3], k);

#pragma unroll
        for (int s = 0; s < 8; s++) {
            float cf[4];
#pragma unroll
            for (int z = 0; z < 4; z++) {
                const float* p1 = &sAux[((s * 16 + k) * 4 + z) * 3];
                cf[z] = p1[0] * p2[z].x + p1[1] * p2[z].y + p1[2] * p2[z].z;
            }
            scoef[s * 256 + t] = make_float4(cf[0], cf[1], cf[2], cf[3]);
        }
    }
    __syncthreads();                           // coef tables ready; mainloop sync-free

    // --- barrier-free stream: 8 slices x 64 KB ---
    const float4* Wbase = (const float4*)W
                        + (((size_t)a * 256 + sub) << 12) + (g * 16 + h4);

    float acc0x = 0.f, acc0y = 0.f, acc0z = 0.f, acc0w = 0.f;
    float acc1x = 0.f, acc1y = 0.f, acc1z = 0.f, acc1w = 0.f;
    float acc2x = 0.f, acc2y = 0.f, acc2z = 0.f, acc2w = 0.f;
    float acc3x = 0.f, acc3y = 0.f, acc3z = 0.f, acc3w = 0.f;

#pragma unroll 1
    for (int s = 0; s < 8; s++) {
        const float4* Wp = Wbase + ((size_t)s << 17);   // +32 slices * 4096 float4
        const float4* cp = scoef + s * 256;

#pragma unroll
        for (int it = 0; it < 16; it += 4) {
            float4 w0 = __ldcs(Wp + (size_t)(it + 0) * 256);
            float4 w1 = __ldcs(Wp + (size_t)(it + 1) * 256);
            float4 w2 = __ldcs(Wp + (size_t)(it + 2) * 256);
            float4 w3 = __ldcs(Wp + (size_t)(it + 3) * 256);

            float4 c;
            c = cp[g + (it + 0) * 16];
            acc0x += c.x * w0.x; acc0y += c.x * w0.y; acc0z += c.x * w0.z; acc0w += c.x * w0.w;
            acc1x += c.y * w0.x; acc1y += c.y * w0.y; acc1z += c.y * w0.z; acc1w += c.y * w0.w;
            acc2x += c.z * w0.x; acc2y += c.z * w0.y; acc2z += c.z * w0.z; acc2w += c.z * w0.w;
            acc3x += c.w * w0.x; acc3y += c.w * w0.y; acc3z += c.w * w0.z; acc3w += c.w * w0.w;

            c = cp[g + (it + 1) * 16];
            acc0x += c.x * w1.x; acc0y += c.x * w1.y; acc0z += c.x * w1.z; acc0w += c.x * w1.w;
            acc1x += c.y * w1.x; acc1y += c.y * w1.y; acc1z += c.y * w1.z; acc1w += c.y * w1.w;
            acc2x += c.z * w1.x; acc2y += c.z * w1.y; acc2z += c.z * w1.z; acc2w += c.z * w1.w;
            acc3x += c.w * w1.x; acc3y += c.w * w1.y; acc3z += c.w * w1.z; acc3w += c.w * w1.w;

            c = cp[g + (it + 2) * 16];
            acc0x += c.x * w2.x; acc0y += c.x * w2.y; acc0z += c.x * w2.z; acc0w += c.x * w2.w;
            acc1x += c.y * w2.x; acc1y += c.y * w2.y; acc1z += c.y * w2.z; acc1w += c.y * w2.w;
            acc2x += c.z * w2.x; acc2y += c.z * w2.y; acc2z += c.z * w2.z; acc2w += c.z * w2.w;
            acc3x += c.w * w2.x; acc3y += c.w * w2.y; acc3z += c.w * w2.z; acc3w += c.w * w2.w;

            c = cp[g + (it + 3) * 16];
            acc0x += c.x * w3.x; acc0y += c.x * w3.y; acc0z += c.x * w3.z; acc0w += c.x * w3.w;
            acc1x += c.y * w3.x; acc1y += c.y * w3.y; acc1z += c.y * w3.z; acc1w += c.y * w3.w;
            acc2x += c.z * w3.x; acc2y += c.z * w3.y; acc2z += c.z * w3.z; acc2w += c.z * w3.w;
            acc3x += c.w * w3.x; acc3y += c.w * w3.y; acc3z += c.w * w3.z; acc3w += c.w * w3.w;
        }
    }

    // --- epilogue: shfl-combine g pairs, 8-warp smem reduce, plain STG ---
#define SHFL_ADD(v) v += __shfl_xor_sync(0xFFFFFFFFu, v, 16)
    SHFL_ADD(acc0x); SHFL_ADD(acc0y); SHFL_ADD(acc0z); SHFL_ADD(acc0w);
    SHFL_ADD(acc1x); SHFL_ADD(acc1y); SHFL_ADD(acc1z); SHFL_ADD(acc1w);
    SHFL_ADD(acc2x); SHFL_ADD(acc2y); SHFL_ADD(acc2z); SHFL_ADD(acc2w);
    SHFL_ADD(acc3x); SHFL_ADD(acc3y); SHFL_ADD(acc3z); SHFL_ADD(acc3w);
#undef SHFL_ADD

    // sAux reuse as sred is safe: its last reads were before the coef sync.
    int lane = t & 31;
    int wrp  = t >> 5;                         // 0..7
    if (lane < 16) {
        float4* r4 = (float4*)sAux;            // [8 warps][4 z][16 h4] of float4
        int base = (wrp * 4) * 16 + h4;
        r4[base + 0 * 16] = make_float4(acc0x, acc0y, acc0z, acc0w);
        r4[base + 1 * 16] = make_float4(acc1x, acc1y, acc1z, acc1w);
        r4[base + 2 * 16] = make_float4(acc2x, acc2y, acc2z, acc2w);
        r4[base + 3 * 16] = make_float4(acc3x, acc3y, acc3z, acc3w);
    }
    __syncthreads();

    float sum = 0.0f;
#pragma unroll
    for (int w2 = 0; w2 < 8; w2++) sum += sAux[w2 * 256 + t];

    g_part[blockIdx.x * 256 + t] = sum;        // coalesced STG, no atomic

    // --- per-a-group last-block-done ---
    __threadfence();                           // my STG visible device-wide
    __syncthreads();                           // all threads' fences done
    if (t == 0) s_old = atomicAdd(&g_count[a], 1);
    __syncthreads();

    if (s_old == 31u)
        finish_group(a, w_fc, b_fc, out, sAux);
}

// ---------------------------------------------------------------------------
extern "C" void kernel_launch(void* const* d_in, const int* in_sizes, int n_in,
                              void* d_out, int out_size) {
    const float* x   = nullptr;
    const float* W   = nullptr;
    const float* wfc = nullptr;
    const float* bfc = nullptr;
    for (int i = 0; i < n_in; i++) {
        long long s = in_sizes[i];
        if      (s == (long long)ZB * NN * 3)                 x   = (const float*)d_in[i];
        else if (s == (long long)NN * NN * NN * NN * NK * NH) W   = (const float*)d_in[i];
        else if (s == NH)                                     wfc = (const float*)d_in[i];
        else if (s == 1)                                      bfc = (const float*)d_in[i];
    }

    k_fused<<<512, 256>>>(W, x, wfc, bfc, (float*)d_out);
}